// round 14
// baseline (speedup 1.0000x reference)
#include <cuda_runtime.h>
#include <cuda_fp16.h>
#include <math.h>
#include <stdint.h>

#define S_TOK 4096
#define H_DIM 2048
#define I_DIM 7168
#define E_NUM 8
#define CAPQ  2048

// GEMM tile config (fp16 operands)
#define BM 128
#define BN 256
#define BK 64                    // halves per K stage (128 bytes/row)
#define NSTAGE 4
#define STAGE_BYTES 49152        // A 16KB + B 32KB
#define SMEM_TOTAL (1024 + NSTAGE * STAGE_BYTES)
#define NTHREADS 512

// ---------------- device scratch ----------
__device__ int    g_e1[S_TOK], g_e2[S_TOK];
__device__ float  g_g1[S_TOK], g_g2[S_TOK];
__device__ int    g_slot1[S_TOK], g_slot2[S_TOK];
__device__ int    g_used[E_NUM];
__device__ __half g_Xh  [(size_t)E_NUM * CAPQ * H_DIM];           // 67 MB
__device__ __half g_W13h[(size_t)E_NUM * 2 * I_DIM * H_DIM];      // 470 MB (row-interleaved w1/w3)
__device__ __half g_W2h [(size_t)E_NUM * H_DIM * I_DIM];          // 235 MB
__device__ __half g_Ah  [(size_t)E_NUM * CAPQ * I_DIM];           // 235 MB
__device__ float  g_Y   [(size_t)E_NUM * CAPQ * H_DIM];           // 134 MB

// ---------------- PTX helpers ----------------
__device__ __forceinline__ uint32_t smem_u32(const void* p) {
    uint32_t a;
    asm("{ .reg .u64 t; cvta.to.shared.u64 t, %1; cvt.u32.u64 %0, t; }" : "=r"(a) : "l"(p));
    return a;
}
__device__ __forceinline__ void cp16(uint32_t dst, const void* src) {
    asm volatile("cp.async.cg.shared.global [%0], [%1], 16;" :: "r"(dst), "l"(src));
}
#define CP_COMMIT() asm volatile("cp.async.commit_group;")
#define CP_WAIT(n)  asm volatile("cp.async.wait_group %0;" :: "n"(n))

#define LDSM4(r0, r1, r2, r3, a) \
    asm volatile("ldmatrix.sync.aligned.m8n8.x4.shared.b16 {%0,%1,%2,%3}, [%4];" \
        : "=r"(r0), "=r"(r1), "=r"(r2), "=r"(r3) : "r"(a))

__device__ __forceinline__ void mma_f16(float* c, const uint32_t* a, const uint32_t* b) {
    asm volatile("mma.sync.aligned.m16n8k16.row.col.f32.f16.f16.f32 "
        "{%0,%1,%2,%3}, {%4,%5,%6,%7}, {%8,%9}, {%0,%1,%2,%3};"
        : "+f"(c[0]), "+f"(c[1]), "+f"(c[2]), "+f"(c[3])
        : "r"(a[0]), "r"(a[1]), "r"(a[2]), "r"(a[3]), "r"(b[0]), "r"(b[1]));
}

#define SWZ(o) ((o) ^ (((o) >> 3) & 0x70))

__device__ __forceinline__ float silu_f(float g) { return g / (1.f + expf(-g)); }

// ---------------- 1) gating ----------------------
__global__ void gate_kernel(const float* __restrict__ x, const float* __restrict__ gw) {
    int s = blockIdx.x;
    int w = threadIdx.x >> 5, lane = threadIdx.x & 31;
    const float* xr = x + (size_t)s * H_DIM;
    const float* gr = gw + (size_t)w * H_DIM;
    float acc = 0.f;
    for (int h = lane; h < H_DIM; h += 32) acc += xr[h] * gr[h];
    #pragma unroll
    for (int o = 16; o; o >>= 1) acc += __shfl_xor_sync(0xffffffff, acc, o);
    __shared__ float logit[E_NUM];
    if (lane == 0) logit[w] = acc;
    __syncthreads();
    if (threadIdx.x == 0) {
        int i1 = 0; float b1 = logit[0];
        #pragma unroll
        for (int e = 1; e < E_NUM; e++) if (logit[e] > b1) { b1 = logit[e]; i1 = e; }
        int i2 = -1; float b2 = -1e30f;
        #pragma unroll
        for (int e = 0; e < E_NUM; e++) if (e != i1 && logit[e] > b2) { b2 = logit[e]; i2 = e; }
        float p2 = expf(b2 - b1);
        float inv = 1.f / (1.f + p2);
        g_e1[s] = i1; g_e2[s] = i2;
        g_g1[s] = inv; g_g2[s] = p2 * inv;
    }
}

// ---------------- 2) routing scan ----------------------------
__global__ void scan_kernel() {
    __shared__ int sh[512][16];
    __shared__ int cnt1[E_NUM];
    int t = threadIdx.x;
    int c[16];
    #pragma unroll
    for (int i = 0; i < 16; i++) c[i] = 0;
    int base = t * 8;
    #pragma unroll
    for (int j = 0; j < 8; j++) { c[g_e1[base + j]]++; c[8 + g_e2[base + j]]++; }
    #pragma unroll
    for (int i = 0; i < 16; i++) sh[t][i] = c[i];
    __syncthreads();
    for (int off = 1; off < 512; off <<= 1) {
        int v[16];
        if (t >= off) {
            #pragma unroll
            for (int i = 0; i < 16; i++) v[i] = sh[t - off][i];
        }
        __syncthreads();
        if (t >= off) {
            #pragma unroll
            for (int i = 0; i < 16; i++) sh[t][i] += v[i];
        }
        __syncthreads();
    }
    if (t == 0) {
        #pragma unroll
        for (int e = 0; e < E_NUM; e++) cnt1[e] = sh[511][e];
    }
    __syncthreads();
    int off1[E_NUM], off2[E_NUM];
    #pragma unroll
    for (int e = 0; e < E_NUM; e++) {
        off1[e] = sh[t][e] - c[e];
        off2[e] = sh[t][8 + e] - c[8 + e];
    }
    #pragma unroll
    for (int j = 0; j < 8; j++) {
        int s = base + j;
        int e1 = g_e1[s], e2 = g_e2[s];
        g_slot1[s] = off1[e1]++;
        g_slot2[s] = cnt1[e2] + off2[e2]++;
    }
    if (t < E_NUM) {
        int u = sh[511][t] + sh[511][8 + t];
        g_used[t] = (u > CAPQ) ? CAPQ : u;
    }
}

// ---------------- 3) dispatch gather (fp32 -> fp16) ------------
__global__ void gather_kernel(const float* __restrict__ x) {
    int b = blockIdx.x;
    int s = b >> 1, ch = b & 1;
    int e    = ch ? g_e2[s]    : g_e1[s];
    int slot = ch ? g_slot2[s] : g_slot1[s];
    if (slot >= CAPQ) return;
    const float4* src = (const float4*)(x + (size_t)s * H_DIM);
    uint2*        dst = (uint2*)(g_Xh + ((size_t)e * CAPQ + slot) * H_DIM);
    for (int i = threadIdx.x; i < H_DIM / 4; i += blockDim.x) {
        float4 v = src[i];
        __half2 h0 = __floats2half2_rn(v.x, v.y);
        __half2 h1 = __floats2half2_rn(v.z, v.w);
        uint2 o; o.x = *(uint32_t*)&h0; o.y = *(uint32_t*)&h1;
        dst[i] = o;
    }
}

// ---------------- 3b) w13 convert + row interleave --------------
// dst row r (within expert): r even -> w1 row r/2; r odd -> w3 row r/2 (src row I + r/2)
__global__ void cvt13_kernel(const float* __restrict__ src) {
    int d = blockIdx.x;                      // dst row, global over E*2I
    int e = d / (2 * I_DIM);
    int r = d - e * 2 * I_DIM;
    int n = (r & 1) ? (I_DIM + (r >> 1)) : (r >> 1);
    const float4* s4 = (const float4*)(src + ((size_t)e * 2 * I_DIM + n) * H_DIM);
    uint2* dst = (uint2*)(g_W13h + (size_t)d * H_DIM);
    for (int i = threadIdx.x; i < H_DIM / 4; i += blockDim.x) {
        float4 v = s4[i];
        __half2 h0 = __floats2half2_rn(v.x, v.y);
        __half2 h1 = __floats2half2_rn(v.z, v.w);
        uint2 o; o.x = *(uint32_t*)&h0; o.y = *(uint32_t*)&h1;
        dst[i] = o;
    }
}

// ---------------- 3c) flat weight convert fp32 -> fp16 ----------
__global__ void cvt_kernel(const float4* __restrict__ src, uint2* __restrict__ dst, int n4) {
    int i = blockIdx.x * blockDim.x + threadIdx.x;
    int stride = gridDim.x * blockDim.x;
    for (; i < n4; i += stride) {
        float4 v = src[i];
        __half2 h0 = __floats2half2_rn(v.x, v.y);
        __half2 h1 = __floats2half2_rn(v.z, v.w);
        uint2 o; o.x = *(uint32_t*)&h0; o.y = *(uint32_t*)&h1;
        dst[i] = o;
    }
}

// ---------------- 4) fp16 mma grouped GEMM NT ------------------
// C[m][n] = sum_k A[m][k]*B[n][k];  128x256 CTA, 16 warps (2x8), warp 64x32
// MODE 0: plain fp32 C  (N = logical cols)
// MODE 1: fused silu(even)*odd -> fp16 out, out cols = N/2, row stride strideO
template <int MODE>
__global__ void __launch_bounds__(NTHREADS, 1) gemm_hmma(
    const __half* __restrict__ Abase, size_t strideA,
    const __half* __restrict__ Bbase, size_t strideB,
    float* __restrict__ Cbase, size_t strideC,
    __half* __restrict__ Obase, size_t strideO,
    int N, int K)    // K in halves
{
    extern __shared__ char smem_raw[];
    int e = blockIdx.z;
    int mrow = blockIdx.x * BM;
    if (mrow >= g_used[e]) return;
    int ncol = blockIdx.y * BN;
    const __half* A = Abase + (size_t)e * strideA + (size_t)mrow * K;
    const __half* B = Bbase + (size_t)e * strideB + (size_t)ncol * K;

    uint32_t sb = (smem_u32(smem_raw) + 1023u) & ~1023u;
    int tid  = threadIdx.x;
    int lane = tid & 31;
    int wid  = tid >> 5;
    int wm = wid >> 3;            // 0..1  (M, 64 rows each)
    int wn = wid & 7;             // 0..7  (N, 32 cols each)

    const int arow = tid >> 2, acb = (tid & 3) * 32;
    const int brow = tid >> 1, bcb = (tid & 1) * 64;
    const __half* Ag = A + (size_t)arow * K + (acb >> 1);
    const __half* Bg = B + (size_t)brow * K + (bcb >> 1);
    uint32_t a_sw[2], b_sw[4];
    #pragma unroll
    for (int j = 0; j < 2; j++) a_sw[j] = SWZ((uint32_t)(arow * 128 + acb + j * 16));
    #pragma unroll
    for (int j = 0; j < 4; j++) b_sw[j] = SWZ((uint32_t)(brow * 128 + bcb + j * 16));

    uint32_t a_off[4];
    #pragma unroll
    for (int i = 0; i < 4; i++) {
        uint32_t r = (uint32_t)(wm * 64 + i * 16 + (lane & 15));
        a_off[i] = r * 128 + ((lane >> 4) & 1) * 16;
    }
    uint32_t b_off[2];
    #pragma unroll
    for (int jp = 0; jp < 2; jp++) {
        uint32_t r = (uint32_t)(wn * 32 + jp * 16 + (lane & 7) + ((lane >> 4) & 1) * 8);
        b_off[jp] = r * 128 + ((lane >> 3) & 1) * 16;
    }

    float acc[4][4][4];
    #pragma unroll
    for (int i = 0; i < 4; i++)
        #pragma unroll
        for (int j = 0; j < 4; j++)
            #pragma unroll
            for (int q = 0; q < 4; q++) acc[i][j][q] = 0.f;

    const int KST = K / BK;

    #pragma unroll
    for (int s = 0; s < NSTAGE - 1; s++) {
        const __half* ag = Ag + s * BK;
        const __half* bg = Bg + s * BK;
        uint32_t ab = sb + s * STAGE_BYTES, bb = ab + 16384;
        #pragma unroll
        for (int j = 0; j < 2; j++) cp16(ab + a_sw[j], ag + j * 8);
        #pragma unroll
        for (int j = 0; j < 4; j++) cp16(bb + b_sw[j], bg + j * 8);
        CP_COMMIT();
    }

    for (int k = 0; k < KST; k++) {
        int buf = k & (NSTAGE - 1);
        CP_WAIT(NSTAGE - 2);
        __syncthreads();

        int ls = k + NSTAGE - 1;
        if (ls < KST) {
            int lb = ls & (NSTAGE - 1);
            const __half* ag = Ag + ls * BK;
            const __half* bg = Bg + ls * BK;
            uint32_t ab = sb + lb * STAGE_BYTES, bb = ab + 16384;
            #pragma unroll
            for (int j = 0; j < 2; j++) cp16(ab + a_sw[j], ag + j * 8);
            #pragma unroll
            for (int j = 0; j < 4; j++) cp16(bb + b_sw[j], bg + j * 8);
        }
        CP_COMMIT();

        uint32_t asb = sb + buf * STAGE_BYTES;
        uint32_t bsb = asb + 16384;
        #pragma unroll
        for (int kb = 0; kb < 4; kb++) {
            uint32_t afrag[4][4], bfrag[4][2];
            #pragma unroll
            for (int i = 0; i < 4; i++) {
                uint32_t addr = asb + SWZ(a_off[i] + kb * 32);
                LDSM4(afrag[i][0], afrag[i][1], afrag[i][2], afrag[i][3], addr);
            }
            #pragma unroll
            for (int jp = 0; jp < 2; jp++) {
                uint32_t addr = bsb + SWZ(b_off[jp] + kb * 32);
                LDSM4(bfrag[2*jp][0], bfrag[2*jp][1], bfrag[2*jp+1][0], bfrag[2*jp+1][1], addr);
            }
            #pragma unroll
            for (int i = 0; i < 4; i++)
                #pragma unroll
                for (int j = 0; j < 4; j++)
                    mma_f16(acc[i][j], afrag[i], bfrag[j]);
        }
    }

    int g  = lane >> 2;
    int t4 = lane & 3;
    if (MODE == 0) {
        float* C = Cbase + (size_t)e * strideC + (size_t)mrow * N + ncol;
        #pragma unroll
        for (int i = 0; i < 4; i++) {
            int r0 = wm * 64 + i * 16 + g;
            #pragma unroll
            for (int j = 0; j < 4; j++) {
                int cb = wn * 32 + j * 8 + 2 * t4;
                float* p0 = C + (size_t)r0 * N + cb;
                float* p1 = p0 + (size_t)8 * N;
                *(float2*)p0 = make_float2(acc[i][j][0], acc[i][j][1]);
                *(float2*)p1 = make_float2(acc[i][j][2], acc[i][j][3]);
            }
        }
    } else {
        // fused: even col = g, odd col = u  ->  silu(g)*u, out col = cb/2
        __half* O = Obase + (size_t)e * strideO * 0 + ((size_t)e * CAPQ + mrow) * strideO + (ncol >> 1);
        #pragma unroll
        for (int i = 0; i < 4; i++) {
            int r0 = wm * 64 + i * 16 + g;
            #pragma unroll
            for (int j = 0; j < 4; j++) {
                int co = wn * 16 + j * 4 + t4;
                __half* p0 = O + (size_t)r0 * strideO + co;
                __half* p1 = p0 + (size_t)8 * strideO;
                *p0 = __float2half_rn(silu_f(acc[i][j][0]) * acc[i][j][1]);
                *p1 = __float2half_rn(silu_f(acc[i][j][2]) * acc[i][j][3]);
            }
        }
    }
}

// ---------------- 6) combine (float4) ---------------------------
__global__ void combine_kernel(float* __restrict__ out) {
    int s = blockIdx.x;
    int e1 = g_e1[s], e2 = g_e2[s];
    int s1 = g_slot1[s], s2 = g_slot2[s];
    float w1 = g_g1[s], w2 = g_g2[s];
    const float4* y1 = (s1 < CAPQ) ? (const float4*)(g_Y + ((size_t)e1 * CAPQ + s1) * H_DIM) : nullptr;
    const float4* y2 = (s2 < CAPQ) ? (const float4*)(g_Y + ((size_t)e2 * CAPQ + s2) * H_DIM) : nullptr;
    float4* o = (float4*)(out + (size_t)s * H_DIM);
    for (int h = threadIdx.x; h < H_DIM / 4; h += blockDim.x) {
        float4 v = make_float4(0.f, 0.f, 0.f, 0.f);
        if (y1) {
            float4 a = y1[h];
            v.x += w1 * a.x; v.y += w1 * a.y; v.z += w1 * a.z; v.w += w1 * a.w;
        }
        if (y2) {
            float4 a = y2[h];
            v.x += w2 * a.x; v.y += w2 * a.y; v.z += w2 * a.z; v.w += w2 * a.w;
        }
        o[h] = v;
    }
}

// ---------------- launch ----------------------------------------
extern "C" void kernel_launch(void* const* d_in, const int* in_sizes, int n_in,
                              void* d_out, int out_size) {
    const float* x   = (const float*)d_in[0];   // [S, H]
    const float* gw  = (const float*)d_in[1];   // [E, H]
    const float* w13 = (const float*)d_in[2];   // [E, 2I, H]
    const float* w2  = (const float*)d_in[3];   // [E, H, I]
    float* out = (float*)d_out;

    __half *Xh, *W13h, *W2h, *Ah;
    float *Yd;
    cudaGetSymbolAddress((void**)&Xh,   g_Xh);
    cudaGetSymbolAddress((void**)&W13h, g_W13h);
    cudaGetSymbolAddress((void**)&W2h,  g_W2h);
    cudaGetSymbolAddress((void**)&Ah,   g_Ah);
    cudaGetSymbolAddress((void**)&Yd,   g_Y);

    static bool attr_set = false;
    if (!attr_set) {
        cudaFuncSetAttribute(gemm_hmma<0>, cudaFuncAttributeMaxDynamicSharedMemorySize, SMEM_TOTAL);
        cudaFuncSetAttribute(gemm_hmma<1>, cudaFuncAttributeMaxDynamicSharedMemorySize, SMEM_TOTAL);
        attr_set = true;
    }

    gate_kernel<<<S_TOK, 256>>>(x, gw);
    scan_kernel<<<1, 512>>>();
    gather_kernel<<<S_TOK * 2, 256>>>(x);

    // weight conversion (w13 row-interleaved, w2 flat)
    cvt13_kernel<<<E_NUM * 2 * I_DIM, 128>>>(w13);
    {
        int n2 = (int)((size_t)E_NUM * H_DIM * I_DIM / 4);
        cvt_kernel<<<4096, 256>>>((const float4*)w2, (uint2*)W2h, n2);
    }

    // GEMM1 fused: Ah[e] = silu(Xh @ w1^T) * (Xh @ w3^T)  (CAP x I fp16)
    {
        dim3 grid(CAPQ / BM, (2 * I_DIM) / BN, E_NUM);
        gemm_hmma<1><<<grid, NTHREADS, SMEM_TOTAL>>>(
            Xh, (size_t)CAPQ * H_DIM,
            W13h, (size_t)2 * I_DIM * H_DIM,
            nullptr, 0,
            Ah, (size_t)I_DIM,
            2 * I_DIM, H_DIM);
    }
    // GEMM2: Y[e] = Ah[e] (CAP x I) @ W2h[e]^T (H x I) -> CAP x H (fp32)
    {
        dim3 grid(CAPQ / BM, H_DIM / BN, E_NUM);
        gemm_hmma<0><<<grid, NTHREADS, SMEM_TOTAL>>>(
            Ah, (size_t)CAPQ * I_DIM,
            W2h, (size_t)H_DIM * I_DIM,
            Yd, (size_t)CAPQ * H_DIM,
            nullptr, 0,
            H_DIM, I_DIM);
    }
    combine_kernel<<<S_TOK, 256>>>(out);
}

// round 15
// speedup vs baseline: 1.0016x; 1.0016x over previous
#include <cuda_runtime.h>
#include <cuda_fp16.h>
#include <math.h>
#include <stdint.h>

#define S_TOK 4096
#define H_DIM 2048
#define I_DIM 7168
#define E_NUM 8
#define CAPQ  2048

// GEMM tile config (fp16 operands)
#define BM 128
#define BN 256
#define BK 64                    // halves per K stage (128 bytes/row)
#define NSTAGE 4
#define STAGE_BYTES 49152        // A 16KB + B 32KB
#define SMEM_TOTAL (1024 + NSTAGE * STAGE_BYTES)
#define NTHREADS 512

// ---------------- device scratch ----------
__device__ int    g_e1[S_TOK], g_e2[S_TOK];
__device__ float  g_g1[S_TOK], g_g2[S_TOK];
__device__ int    g_slot1[S_TOK], g_slot2[S_TOK];
__device__ int    g_used[E_NUM];
__device__ __half g_Xh  [(size_t)E_NUM * CAPQ * H_DIM];           // 67 MB
__device__ __half g_W13h[(size_t)E_NUM * 2 * I_DIM * H_DIM];      // 470 MB (row-interleaved w1/w3)
__device__ __half g_W2h [(size_t)E_NUM * H_DIM * I_DIM];          // 235 MB
__device__ __half g_Ah  [(size_t)E_NUM * CAPQ * I_DIM];           // 235 MB
__device__ float  g_Y   [(size_t)E_NUM * CAPQ * H_DIM];           // 134 MB

// ---------------- PTX helpers ----------------
__device__ __forceinline__ uint32_t smem_u32(const void* p) {
    uint32_t a;
    asm("{ .reg .u64 t; cvta.to.shared.u64 t, %1; cvt.u32.u64 %0, t; }" : "=r"(a) : "l"(p));
    return a;
}
__device__ __forceinline__ void cp16(uint32_t dst, const void* src) {
    asm volatile("cp.async.cg.shared.global [%0], [%1], 16;" :: "r"(dst), "l"(src));
}
#define CP_COMMIT() asm volatile("cp.async.commit_group;")
#define CP_WAIT(n)  asm volatile("cp.async.wait_group %0;" :: "n"(n))

#define LDSM4(r0, r1, r2, r3, a) \
    asm volatile("ldmatrix.sync.aligned.m8n8.x4.shared.b16 {%0,%1,%2,%3}, [%4];" \
        : "=r"(r0), "=r"(r1), "=r"(r2), "=r"(r3) : "r"(a))

__device__ __forceinline__ void mma_f16(float* c, const uint32_t* a, const uint32_t* b) {
    asm volatile("mma.sync.aligned.m16n8k16.row.col.f32.f16.f16.f32 "
        "{%0,%1,%2,%3}, {%4,%5,%6,%7}, {%8,%9}, {%0,%1,%2,%3};"
        : "+f"(c[0]), "+f"(c[1]), "+f"(c[2]), "+f"(c[3])
        : "r"(a[0]), "r"(a[1]), "r"(a[2]), "r"(a[3]), "r"(b[0]), "r"(b[1]));
}

#define SWZ(o) ((o) ^ (((o) >> 3) & 0x70))

__device__ __forceinline__ float silu_f(float g) { return g / (1.f + expf(-g)); }

// ---------------- 1) gating ----------------------
__global__ void gate_kernel(const float* __restrict__ x, const float* __restrict__ gw) {
    int s = blockIdx.x;
    int w = threadIdx.x >> 5, lane = threadIdx.x & 31;
    const float* xr = x + (size_t)s * H_DIM;
    const float* gr = gw + (size_t)w * H_DIM;
    float acc = 0.f;
    for (int h = lane; h < H_DIM; h += 32) acc += xr[h] * gr[h];
    #pragma unroll
    for (int o = 16; o; o >>= 1) acc += __shfl_xor_sync(0xffffffff, acc, o);
    __shared__ float logit[E_NUM];
    if (lane == 0) logit[w] = acc;
    __syncthreads();
    if (threadIdx.x == 0) {
        int i1 = 0; float b1 = logit[0];
        #pragma unroll
        for (int e = 1; e < E_NUM; e++) if (logit[e] > b1) { b1 = logit[e]; i1 = e; }
        int i2 = -1; float b2 = -1e30f;
        #pragma unroll
        for (int e = 0; e < E_NUM; e++) if (e != i1 && logit[e] > b2) { b2 = logit[e]; i2 = e; }
        float p2 = expf(b2 - b1);
        float inv = 1.f / (1.f + p2);
        g_e1[s] = i1; g_e2[s] = i2;
        g_g1[s] = inv; g_g2[s] = p2 * inv;
    }
}

// ---------------- 2) routing scan ----------------------------
__global__ void scan_kernel() {
    __shared__ int sh[512][16];
    __shared__ int cnt1[E_NUM];
    int t = threadIdx.x;
    int c[16];
    #pragma unroll
    for (int i = 0; i < 16; i++) c[i] = 0;
    int base = t * 8;
    #pragma unroll
    for (int j = 0; j < 8; j++) { c[g_e1[base + j]]++; c[8 + g_e2[base + j]]++; }
    #pragma unroll
    for (int i = 0; i < 16; i++) sh[t][i] = c[i];
    __syncthreads();
    for (int off = 1; off < 512; off <<= 1) {
        int v[16];
        if (t >= off) {
            #pragma unroll
            for (int i = 0; i < 16; i++) v[i] = sh[t - off][i];
        }
        __syncthreads();
        if (t >= off) {
            #pragma unroll
            for (int i = 0; i < 16; i++) sh[t][i] += v[i];
        }
        __syncthreads();
    }
    if (t == 0) {
        #pragma unroll
        for (int e = 0; e < E_NUM; e++) cnt1[e] = sh[511][e];
    }
    __syncthreads();
    int off1[E_NUM], off2[E_NUM];
    #pragma unroll
    for (int e = 0; e < E_NUM; e++) {
        off1[e] = sh[t][e] - c[e];
        off2[e] = sh[t][8 + e] - c[8 + e];
    }
    #pragma unroll
    for (int j = 0; j < 8; j++) {
        int s = base + j;
        int e1 = g_e1[s], e2 = g_e2[s];
        g_slot1[s] = off1[e1]++;
        g_slot2[s] = cnt1[e2] + off2[e2]++;
    }
    if (t < E_NUM) {
        int u = sh[511][t] + sh[511][8 + t];
        g_used[t] = (u > CAPQ) ? CAPQ : u;
    }
}

// ---------------- 3) dispatch gather (fp32 -> fp16) ------------
__global__ void gather_kernel(const float* __restrict__ x) {
    int b = blockIdx.x;
    int s = b >> 1, ch = b & 1;
    int e    = ch ? g_e2[s]    : g_e1[s];
    int slot = ch ? g_slot2[s] : g_slot1[s];
    if (slot >= CAPQ) return;
    const float4* src = (const float4*)(x + (size_t)s * H_DIM);
    uint2*        dst = (uint2*)(g_Xh + ((size_t)e * CAPQ + slot) * H_DIM);
    for (int i = threadIdx.x; i < H_DIM / 4; i += blockDim.x) {
        float4 v = src[i];
        __half2 h0 = __floats2half2_rn(v.x, v.y);
        __half2 h1 = __floats2half2_rn(v.z, v.w);
        uint2 o; o.x = *(uint32_t*)&h0; o.y = *(uint32_t*)&h1;
        dst[i] = o;
    }
}

// ---------------- 3b) w13 convert + row interleave --------------
// dst row r (within expert): r even -> w1 row r/2; r odd -> w3 row r/2 (src row I + r/2)
__global__ void cvt13_kernel(const float* __restrict__ src) {
    int d = blockIdx.x;                      // dst row, global over E*2I
    int e = d / (2 * I_DIM);
    int r = d - e * 2 * I_DIM;
    int n = (r & 1) ? (I_DIM + (r >> 1)) : (r >> 1);
    const float4* s4 = (const float4*)(src + ((size_t)e * 2 * I_DIM + n) * H_DIM);
    uint2* dst = (uint2*)(g_W13h + (size_t)d * H_DIM);
    for (int i = threadIdx.x; i < H_DIM / 4; i += blockDim.x) {
        float4 v = s4[i];
        __half2 h0 = __floats2half2_rn(v.x, v.y);
        __half2 h1 = __floats2half2_rn(v.z, v.w);
        uint2 o; o.x = *(uint32_t*)&h0; o.y = *(uint32_t*)&h1;
        dst[i] = o;
    }
}

// ---------------- 3c) flat weight convert fp32 -> fp16 ----------
__global__ void cvt_kernel(const float4* __restrict__ src, uint2* __restrict__ dst, int n4) {
    int i = blockIdx.x * blockDim.x + threadIdx.x;
    int stride = gridDim.x * blockDim.x;
    for (; i < n4; i += stride) {
        float4 v = src[i];
        __half2 h0 = __floats2half2_rn(v.x, v.y);
        __half2 h1 = __floats2half2_rn(v.z, v.w);
        uint2 o; o.x = *(uint32_t*)&h0; o.y = *(uint32_t*)&h1;
        dst[i] = o;
    }
}

// ---------------- 4) fp16 mma grouped GEMM NT ------------------
// C[m][n] = sum_k A[m][k]*B[n][k];  128x256 CTA, 16 warps (2x8), warp 64x32
// MODE 0: plain fp32 C  (N = logical cols)
// MODE 1: fused silu(even)*odd -> fp16 out, out cols = N/2, row stride strideO
template <int MODE>
__global__ void __launch_bounds__(NTHREADS, 1) gemm_hmma(
    const __half* __restrict__ Abase, size_t strideA,
    const __half* __restrict__ Bbase, size_t strideB,
    float* __restrict__ Cbase, size_t strideC,
    __half* __restrict__ Obase, size_t strideO,
    int N, int K)    // K in halves
{
    extern __shared__ char smem_raw[];
    int e = blockIdx.z;
    int mrow = blockIdx.x * BM;
    if (mrow >= g_used[e]) return;
    int ncol = blockIdx.y * BN;
    const __half* A = Abase + (size_t)e * strideA + (size_t)mrow * K;
    const __half* B = Bbase + (size_t)e * strideB + (size_t)ncol * K;

    uint32_t sb = (smem_u32(smem_raw) + 1023u) & ~1023u;
    int tid  = threadIdx.x;
    int lane = tid & 31;
    int wid  = tid >> 5;
    int wm = wid >> 3;            // 0..1  (M, 64 rows each)
    int wn = wid & 7;             // 0..7  (N, 32 cols each)

    const int arow = tid >> 2, acb = (tid & 3) * 32;
    const int brow = tid >> 1, bcb = (tid & 1) * 64;
    const __half* Ag = A + (size_t)arow * K + (acb >> 1);
    const __half* Bg = B + (size_t)brow * K + (bcb >> 1);
    uint32_t a_sw[2], b_sw[4];
    #pragma unroll
    for (int j = 0; j < 2; j++) a_sw[j] = SWZ((uint32_t)(arow * 128 + acb + j * 16));
    #pragma unroll
    for (int j = 0; j < 4; j++) b_sw[j] = SWZ((uint32_t)(brow * 128 + bcb + j * 16));

    uint32_t a_off[4];
    #pragma unroll
    for (int i = 0; i < 4; i++) {
        uint32_t r = (uint32_t)(wm * 64 + i * 16 + (lane & 15));
        a_off[i] = r * 128 + ((lane >> 4) & 1) * 16;
    }
    uint32_t b_off[2];
    #pragma unroll
    for (int jp = 0; jp < 2; jp++) {
        uint32_t r = (uint32_t)(wn * 32 + jp * 16 + (lane & 7) + ((lane >> 4) & 1) * 8);
        b_off[jp] = r * 128 + ((lane >> 3) & 1) * 16;
    }

    float acc[4][4][4];
    #pragma unroll
    for (int i = 0; i < 4; i++)
        #pragma unroll
        for (int j = 0; j < 4; j++)
            #pragma unroll
            for (int q = 0; q < 4; q++) acc[i][j][q] = 0.f;

    const int KST = K / BK;

    #pragma unroll
    for (int s = 0; s < NSTAGE - 1; s++) {
        const __half* ag = Ag + s * BK;
        const __half* bg = Bg + s * BK;
        uint32_t ab = sb + s * STAGE_BYTES, bb = ab + 16384;
        #pragma unroll
        for (int j = 0; j < 2; j++) cp16(ab + a_sw[j], ag + j * 8);
        #pragma unroll
        for (int j = 0; j < 4; j++) cp16(bb + b_sw[j], bg + j * 8);
        CP_COMMIT();
    }

    for (int k = 0; k < KST; k++) {
        int buf = k & (NSTAGE - 1);
        CP_WAIT(NSTAGE - 2);
        __syncthreads();

        int ls = k + NSTAGE - 1;
        if (ls < KST) {
            int lb = ls & (NSTAGE - 1);
            const __half* ag = Ag + ls * BK;
            const __half* bg = Bg + ls * BK;
            uint32_t ab = sb + lb * STAGE_BYTES, bb = ab + 16384;
            #pragma unroll
            for (int j = 0; j < 2; j++) cp16(ab + a_sw[j], ag + j * 8);
            #pragma unroll
            for (int j = 0; j < 4; j++) cp16(bb + b_sw[j], bg + j * 8);
        }
        CP_COMMIT();

        uint32_t asb = sb + buf * STAGE_BYTES;
        uint32_t bsb = asb + 16384;
        #pragma unroll
        for (int kb = 0; kb < 4; kb++) {
            uint32_t afrag[4][4], bfrag[4][2];
            #pragma unroll
            for (int i = 0; i < 4; i++) {
                uint32_t addr = asb + SWZ(a_off[i] + kb * 32);
                LDSM4(afrag[i][0], afrag[i][1], afrag[i][2], afrag[i][3], addr);
            }
            #pragma unroll
            for (int jp = 0; jp < 2; jp++) {
                uint32_t addr = bsb + SWZ(b_off[jp] + kb * 32);
                LDSM4(bfrag[2*jp][0], bfrag[2*jp][1], bfrag[2*jp+1][0], bfrag[2*jp+1][1], addr);
            }
            #pragma unroll
            for (int i = 0; i < 4; i++)
                #pragma unroll
                for (int j = 0; j < 4; j++)
                    mma_f16(acc[i][j], afrag[i], bfrag[j]);
        }
    }

    int g  = lane >> 2;
    int t4 = lane & 3;
    if (MODE == 0) {
        float* C = Cbase + (size_t)e * strideC + (size_t)mrow * N + ncol;
        #pragma unroll
        for (int i = 0; i < 4; i++) {
            int r0 = wm * 64 + i * 16 + g;
            #pragma unroll
            for (int j = 0; j < 4; j++) {
                int cb = wn * 32 + j * 8 + 2 * t4;
                float* p0 = C + (size_t)r0 * N + cb;
                float* p1 = p0 + (size_t)8 * N;
                *(float2*)p0 = make_float2(acc[i][j][0], acc[i][j][1]);
                *(float2*)p1 = make_float2(acc[i][j][2], acc[i][j][3]);
            }
        }
    } else {
        // fused: even col = g, odd col = u  ->  silu(g)*u, out col = cb/2
        __half* O = Obase + (size_t)e * strideO * 0 + ((size_t)e * CAPQ + mrow) * strideO + (ncol >> 1);
        #pragma unroll
        for (int i = 0; i < 4; i++) {
            int r0 = wm * 64 + i * 16 + g;
            #pragma unroll
            for (int j = 0; j < 4; j++) {
                int co = wn * 16 + j * 4 + t4;
                __half* p0 = O + (size_t)r0 * strideO + co;
                __half* p1 = p0 + (size_t)8 * strideO;
                *p0 = __float2half_rn(silu_f(acc[i][j][0]) * acc[i][j][1]);
                *p1 = __float2half_rn(silu_f(acc[i][j][2]) * acc[i][j][3]);
            }
        }
    }
}

// ---------------- 6) combine (float4) ---------------------------
__global__ void combine_kernel(float* __restrict__ out) {
    int s = blockIdx.x;
    int e1 = g_e1[s], e2 = g_e2[s];
    int s1 = g_slot1[s], s2 = g_slot2[s];
    float w1 = g_g1[s], w2 = g_g2[s];
    const float4* y1 = (s1 < CAPQ) ? (const float4*)(g_Y + ((size_t)e1 * CAPQ + s1) * H_DIM) : nullptr;
    const float4* y2 = (s2 < CAPQ) ? (const float4*)(g_Y + ((size_t)e2 * CAPQ + s2) * H_DIM) : nullptr;
    float4* o = (float4*)(out + (size_t)s * H_DIM);
    for (int h = threadIdx.x; h < H_DIM / 4; h += blockDim.x) {
        float4 v = make_float4(0.f, 0.f, 0.f, 0.f);
        if (y1) {
            float4 a = y1[h];
            v.x += w1 * a.x; v.y += w1 * a.y; v.z += w1 * a.z; v.w += w1 * a.w;
        }
        if (y2) {
            float4 a = y2[h];
            v.x += w2 * a.x; v.y += w2 * a.y; v.z += w2 * a.z; v.w += w2 * a.w;
        }
        o[h] = v;
    }
}

// ---------------- launch ----------------------------------------
extern "C" void kernel_launch(void* const* d_in, const int* in_sizes, int n_in,
                              void* d_out, int out_size) {
    const float* x   = (const float*)d_in[0];   // [S, H]
    const float* gw  = (const float*)d_in[1];   // [E, H]
    const float* w13 = (const float*)d_in[2];   // [E, 2I, H]
    const float* w2  = (const float*)d_in[3];   // [E, H, I]
    float* out = (float*)d_out;

    __half *Xh, *W13h, *W2h, *Ah;
    float *Yd;
    cudaGetSymbolAddress((void**)&Xh,   g_Xh);
    cudaGetSymbolAddress((void**)&W13h, g_W13h);
    cudaGetSymbolAddress((void**)&W2h,  g_W2h);
    cudaGetSymbolAddress((void**)&Ah,   g_Ah);
    cudaGetSymbolAddress((void**)&Yd,   g_Y);

    static bool attr_set = false;
    if (!attr_set) {
        cudaFuncSetAttribute(gemm_hmma<0>, cudaFuncAttributeMaxDynamicSharedMemorySize, SMEM_TOTAL);
        cudaFuncSetAttribute(gemm_hmma<1>, cudaFuncAttributeMaxDynamicSharedMemorySize, SMEM_TOTAL);
        attr_set = true;
    }

    gate_kernel<<<S_TOK, 256>>>(x, gw);
    scan_kernel<<<1, 512>>>();
    gather_kernel<<<S_TOK * 2, 256>>>(x);

    // weight conversion (w13 row-interleaved, w2 flat)
    cvt13_kernel<<<E_NUM * 2 * I_DIM, 128>>>(w13);
    {
        int n2 = (int)((size_t)E_NUM * H_DIM * I_DIM / 4);
        cvt_kernel<<<4096, 256>>>((const float4*)w2, (uint2*)W2h, n2);
    }

    // GEMM1 fused: Ah[e] = silu(Xh @ w1^T) * (Xh @ w3^T)  (CAP x I fp16)
    {
        dim3 grid(CAPQ / BM, (2 * I_DIM) / BN, E_NUM);
        gemm_hmma<1><<<grid, NTHREADS, SMEM_TOTAL>>>(
            Xh, (size_t)CAPQ * H_DIM,
            W13h, (size_t)2 * I_DIM * H_DIM,
            nullptr, 0,
            Ah, (size_t)I_DIM,
            2 * I_DIM, H_DIM);
    }
    // GEMM2: Y[e] = Ah[e] (CAP x I) @ W2h[e]^T (H x I) -> CAP x H (fp32)
    {
        dim3 grid(CAPQ / BM, H_DIM / BN, E_NUM);
        gemm_hmma<0><<<grid, NTHREADS, SMEM_TOTAL>>>(
            Ah, (size_t)CAPQ * I_DIM,
            W2h, (size_t)H_DIM * I_DIM,
            Yd, (size_t)CAPQ * H_DIM,
            nullptr, 0,
            H_DIM, I_DIM);
    }
    combine_kernel<<<S_TOK, 256>>>(out);
}

// round 16
// speedup vs baseline: 1.0017x; 1.0001x over previous
#include <cuda_runtime.h>
#include <cuda_fp16.h>
#include <math.h>
#include <stdint.h>

#define S_TOK 4096
#define H_DIM 2048
#define I_DIM 7168
#define E_NUM 8
#define CAPQ  2048

// GEMM tile config (fp16 operands)
#define BM 128
#define BN 256
#define BK 64                    // halves per K stage (128 bytes/row)
#define NSTAGE 4
#define STAGE_BYTES 49152        // A 16KB + B 32KB
#define SMEM_TOTAL (1024 + NSTAGE * STAGE_BYTES)
#define NTHREADS 512

// ---------------- device scratch ----------
__device__ int    g_e1[S_TOK], g_e2[S_TOK];
__device__ float  g_g1[S_TOK], g_g2[S_TOK];
__device__ int    g_slot1[S_TOK], g_slot2[S_TOK];
__device__ int    g_used[E_NUM];
__device__ __half g_Xh  [(size_t)E_NUM * CAPQ * H_DIM];           // 67 MB
__device__ __half g_W13h[(size_t)E_NUM * 2 * I_DIM * H_DIM];      // 470 MB (row-interleaved w1/w3)
__device__ __half g_W2h [(size_t)E_NUM * H_DIM * I_DIM];          // 235 MB
__device__ __half g_Ah  [(size_t)E_NUM * CAPQ * I_DIM];           // 235 MB
__device__ float  g_Y   [(size_t)E_NUM * CAPQ * H_DIM];           // 134 MB

// ---------------- PTX helpers ----------------
__device__ __forceinline__ uint32_t smem_u32(const void* p) {
    uint32_t a;
    asm("{ .reg .u64 t; cvta.to.shared.u64 t, %1; cvt.u32.u64 %0, t; }" : "=r"(a) : "l"(p));
    return a;
}
__device__ __forceinline__ void cp16(uint32_t dst, const void* src) {
    asm volatile("cp.async.cg.shared.global [%0], [%1], 16;" :: "r"(dst), "l"(src));
}
#define CP_COMMIT() asm volatile("cp.async.commit_group;")
#define CP_WAIT(n)  asm volatile("cp.async.wait_group %0;" :: "n"(n))

#define LDSM4(r0, r1, r2, r3, a) \
    asm volatile("ldmatrix.sync.aligned.m8n8.x4.shared.b16 {%0,%1,%2,%3}, [%4];" \
        : "=r"(r0), "=r"(r1), "=r"(r2), "=r"(r3) : "r"(a))

__device__ __forceinline__ void mma_f16(float* c, const uint32_t* a, const uint32_t* b) {
    asm volatile("mma.sync.aligned.m16n8k16.row.col.f32.f16.f16.f32 "
        "{%0,%1,%2,%3}, {%4,%5,%6,%7}, {%8,%9}, {%0,%1,%2,%3};"
        : "+f"(c[0]), "+f"(c[1]), "+f"(c[2]), "+f"(c[3])
        : "r"(a[0]), "r"(a[1]), "r"(a[2]), "r"(a[3]), "r"(b[0]), "r"(b[1]));
}

#define SWZ(o) ((o) ^ (((o) >> 3) & 0x70))

__device__ __forceinline__ float silu_f(float g) { return g / (1.f + expf(-g)); }

// ---------------- 1) gating ----------------------
__global__ void gate_kernel(const float* __restrict__ x, const float* __restrict__ gw) {
    int s = blockIdx.x;
    int w = threadIdx.x >> 5, lane = threadIdx.x & 31;
    const float* xr = x + (size_t)s * H_DIM;
    const float* gr = gw + (size_t)w * H_DIM;
    float acc = 0.f;
    for (int h = lane; h < H_DIM; h += 32) acc += xr[h] * gr[h];
    #pragma unroll
    for (int o = 16; o; o >>= 1) acc += __shfl_xor_sync(0xffffffff, acc, o);
    __shared__ float logit[E_NUM];
    if (lane == 0) logit[w] = acc;
    __syncthreads();
    if (threadIdx.x == 0) {
        int i1 = 0; float b1 = logit[0];
        #pragma unroll
        for (int e = 1; e < E_NUM; e++) if (logit[e] > b1) { b1 = logit[e]; i1 = e; }
        int i2 = -1; float b2 = -1e30f;
        #pragma unroll
        for (int e = 0; e < E_NUM; e++) if (e != i1 && logit[e] > b2) { b2 = logit[e]; i2 = e; }
        float p2 = expf(b2 - b1);
        float inv = 1.f / (1.f + p2);
        g_e1[s] = i1; g_e2[s] = i2;
        g_g1[s] = inv; g_g2[s] = p2 * inv;
    }
}

// ---------------- 2) routing scan ----------------------------
__global__ void scan_kernel() {
    __shared__ int sh[512][16];
    __shared__ int cnt1[E_NUM];
    int t = threadIdx.x;
    int c[16];
    #pragma unroll
    for (int i = 0; i < 16; i++) c[i] = 0;
    int base = t * 8;
    #pragma unroll
    for (int j = 0; j < 8; j++) { c[g_e1[base + j]]++; c[8 + g_e2[base + j]]++; }
    #pragma unroll
    for (int i = 0; i < 16; i++) sh[t][i] = c[i];
    __syncthreads();
    for (int off = 1; off < 512; off <<= 1) {
        int v[16];
        if (t >= off) {
            #pragma unroll
            for (int i = 0; i < 16; i++) v[i] = sh[t - off][i];
        }
        __syncthreads();
        if (t >= off) {
            #pragma unroll
            for (int i = 0; i < 16; i++) sh[t][i] += v[i];
        }
        __syncthreads();
    }
    if (t == 0) {
        #pragma unroll
        for (int e = 0; e < E_NUM; e++) cnt1[e] = sh[511][e];
    }
    __syncthreads();
    int off1[E_NUM], off2[E_NUM];
    #pragma unroll
    for (int e = 0; e < E_NUM; e++) {
        off1[e] = sh[t][e] - c[e];
        off2[e] = sh[t][8 + e] - c[8 + e];
    }
    #pragma unroll
    for (int j = 0; j < 8; j++) {
        int s = base + j;
        int e1 = g_e1[s], e2 = g_e2[s];
        g_slot1[s] = off1[e1]++;
        g_slot2[s] = cnt1[e2] + off2[e2]++;
    }
    if (t < E_NUM) {
        int u = sh[511][t] + sh[511][8 + t];
        g_used[t] = (u > CAPQ) ? CAPQ : u;
    }
}

// ---------------- 3) dispatch gather (fp32 -> fp16) ------------
__global__ void gather_kernel(const float* __restrict__ x) {
    int b = blockIdx.x;
    int s = b >> 1, ch = b & 1;
    int e    = ch ? g_e2[s]    : g_e1[s];
    int slot = ch ? g_slot2[s] : g_slot1[s];
    if (slot >= CAPQ) return;
    const float4* src = (const float4*)(x + (size_t)s * H_DIM);
    uint2*        dst = (uint2*)(g_Xh + ((size_t)e * CAPQ + slot) * H_DIM);
    for (int i = threadIdx.x; i < H_DIM / 4; i += blockDim.x) {
        float4 v = src[i];
        __half2 h0 = __floats2half2_rn(v.x, v.y);
        __half2 h1 = __floats2half2_rn(v.z, v.w);
        uint2 o; o.x = *(uint32_t*)&h0; o.y = *(uint32_t*)&h1;
        dst[i] = o;
    }
}

// ---------------- 3b) w13 convert + row interleave --------------
// dst row r (within expert): r even -> w1 row r/2; r odd -> w3 row r/2 (src row I + r/2)
__global__ void cvt13_kernel(const float* __restrict__ src) {
    int d = blockIdx.x;                      // dst row, global over E*2I
    int e = d / (2 * I_DIM);
    int r = d - e * 2 * I_DIM;
    int n = (r & 1) ? (I_DIM + (r >> 1)) : (r >> 1);
    const float4* s4 = (const float4*)(src + ((size_t)e * 2 * I_DIM + n) * H_DIM);
    uint2* dst = (uint2*)(g_W13h + (size_t)d * H_DIM);
    for (int i = threadIdx.x; i < H_DIM / 4; i += blockDim.x) {
        float4 v = s4[i];
        __half2 h0 = __floats2half2_rn(v.x, v.y);
        __half2 h1 = __floats2half2_rn(v.z, v.w);
        uint2 o; o.x = *(uint32_t*)&h0; o.y = *(uint32_t*)&h1;
        dst[i] = o;
    }
}

// ---------------- 3c) flat weight convert fp32 -> fp16 ----------
__global__ void cvt_kernel(const float4* __restrict__ src, uint2* __restrict__ dst, int n4) {
    int i = blockIdx.x * blockDim.x + threadIdx.x;
    int stride = gridDim.x * blockDim.x;
    for (; i < n4; i += stride) {
        float4 v = src[i];
        __half2 h0 = __floats2half2_rn(v.x, v.y);
        __half2 h1 = __floats2half2_rn(v.z, v.w);
        uint2 o; o.x = *(uint32_t*)&h0; o.y = *(uint32_t*)&h1;
        dst[i] = o;
    }
}

// ---------------- 4) fp16 mma grouped GEMM NT ------------------
// C[m][n] = sum_k A[m][k]*B[n][k];  128x256 CTA, 16 warps (2x8), warp 64x32
// MODE 0: plain fp32 C  (N = logical cols)
// MODE 1: fused silu(even)*odd -> fp16 out, out cols = N/2, row stride strideO
template <int MODE>
__global__ void __launch_bounds__(NTHREADS, 1) gemm_hmma(
    const __half* __restrict__ Abase, size_t strideA,
    const __half* __restrict__ Bbase, size_t strideB,
    float* __restrict__ Cbase, size_t strideC,
    __half* __restrict__ Obase, size_t strideO,
    int N, int K)    // K in halves
{
    extern __shared__ char smem_raw[];
    int e = blockIdx.z;
    int mrow = blockIdx.x * BM;
    if (mrow >= g_used[e]) return;
    int ncol = blockIdx.y * BN;
    const __half* A = Abase + (size_t)e * strideA + (size_t)mrow * K;
    const __half* B = Bbase + (size_t)e * strideB + (size_t)ncol * K;

    uint32_t sb = (smem_u32(smem_raw) + 1023u) & ~1023u;
    int tid  = threadIdx.x;
    int lane = tid & 31;
    int wid  = tid >> 5;
    int wm = wid >> 3;            // 0..1  (M, 64 rows each)
    int wn = wid & 7;             // 0..7  (N, 32 cols each)

    const int arow = tid >> 2, acb = (tid & 3) * 32;
    const int brow = tid >> 1, bcb = (tid & 1) * 64;
    const __half* Ag = A + (size_t)arow * K + (acb >> 1);
    const __half* Bg = B + (size_t)brow * K + (bcb >> 1);
    uint32_t a_sw[2], b_sw[4];
    #pragma unroll
    for (int j = 0; j < 2; j++) a_sw[j] = SWZ((uint32_t)(arow * 128 + acb + j * 16));
    #pragma unroll
    for (int j = 0; j < 4; j++) b_sw[j] = SWZ((uint32_t)(brow * 128 + bcb + j * 16));

    uint32_t a_off[4];
    #pragma unroll
    for (int i = 0; i < 4; i++) {
        uint32_t r = (uint32_t)(wm * 64 + i * 16 + (lane & 15));
        a_off[i] = r * 128 + ((lane >> 4) & 1) * 16;
    }
    uint32_t b_off[2];
    #pragma unroll
    for (int jp = 0; jp < 2; jp++) {
        uint32_t r = (uint32_t)(wn * 32 + jp * 16 + (lane & 7) + ((lane >> 4) & 1) * 8);
        b_off[jp] = r * 128 + ((lane >> 3) & 1) * 16;
    }

    float acc[4][4][4];
    #pragma unroll
    for (int i = 0; i < 4; i++)
        #pragma unroll
        for (int j = 0; j < 4; j++)
            #pragma unroll
            for (int q = 0; q < 4; q++) acc[i][j][q] = 0.f;

    const int KST = K / BK;

    #pragma unroll
    for (int s = 0; s < NSTAGE - 1; s++) {
        const __half* ag = Ag + s * BK;
        const __half* bg = Bg + s * BK;
        uint32_t ab = sb + s * STAGE_BYTES, bb = ab + 16384;
        #pragma unroll
        for (int j = 0; j < 2; j++) cp16(ab + a_sw[j], ag + j * 8);
        #pragma unroll
        for (int j = 0; j < 4; j++) cp16(bb + b_sw[j], bg + j * 8);
        CP_COMMIT();
    }

    for (int k = 0; k < KST; k++) {
        int buf = k & (NSTAGE - 1);
        CP_WAIT(NSTAGE - 2);
        __syncthreads();

        int ls = k + NSTAGE - 1;
        if (ls < KST) {
            int lb = ls & (NSTAGE - 1);
            const __half* ag = Ag + ls * BK;
            const __half* bg = Bg + ls * BK;
            uint32_t ab = sb + lb * STAGE_BYTES, bb = ab + 16384;
            #pragma unroll
            for (int j = 0; j < 2; j++) cp16(ab + a_sw[j], ag + j * 8);
            #pragma unroll
            for (int j = 0; j < 4; j++) cp16(bb + b_sw[j], bg + j * 8);
        }
        CP_COMMIT();

        uint32_t asb = sb + buf * STAGE_BYTES;
        uint32_t bsb = asb + 16384;
        #pragma unroll
        for (int kb = 0; kb < 4; kb++) {
            uint32_t afrag[4][4], bfrag[4][2];
            #pragma unroll
            for (int i = 0; i < 4; i++) {
                uint32_t addr = asb + SWZ(a_off[i] + kb * 32);
                LDSM4(afrag[i][0], afrag[i][1], afrag[i][2], afrag[i][3], addr);
            }
            #pragma unroll
            for (int jp = 0; jp < 2; jp++) {
                uint32_t addr = bsb + SWZ(b_off[jp] + kb * 32);
                LDSM4(bfrag[2*jp][0], bfrag[2*jp][1], bfrag[2*jp+1][0], bfrag[2*jp+1][1], addr);
            }
            #pragma unroll
            for (int i = 0; i < 4; i++)
                #pragma unroll
                for (int j = 0; j < 4; j++)
                    mma_f16(acc[i][j], afrag[i], bfrag[j]);
        }
    }

    int g  = lane >> 2;
    int t4 = lane & 3;
    if (MODE == 0) {
        float* C = Cbase + (size_t)e * strideC + (size_t)mrow * N + ncol;
        #pragma unroll
        for (int i = 0; i < 4; i++) {
            int r0 = wm * 64 + i * 16 + g;
            #pragma unroll
            for (int j = 0; j < 4; j++) {
                int cb = wn * 32 + j * 8 + 2 * t4;
                float* p0 = C + (size_t)r0 * N + cb;
                float* p1 = p0 + (size_t)8 * N;
                *(float2*)p0 = make_float2(acc[i][j][0], acc[i][j][1]);
                *(float2*)p1 = make_float2(acc[i][j][2], acc[i][j][3]);
            }
        }
    } else {
        // fused: even col = g, odd col = u  ->  silu(g)*u, out col = cb/2
        __half* O = Obase + (size_t)e * strideO * 0 + ((size_t)e * CAPQ + mrow) * strideO + (ncol >> 1);
        #pragma unroll
        for (int i = 0; i < 4; i++) {
            int r0 = wm * 64 + i * 16 + g;
            #pragma unroll
            for (int j = 0; j < 4; j++) {
                int co = wn * 16 + j * 4 + t4;
                __half* p0 = O + (size_t)r0 * strideO + co;
                __half* p1 = p0 + (size_t)8 * strideO;
                *p0 = __float2half_rn(silu_f(acc[i][j][0]) * acc[i][j][1]);
                *p1 = __float2half_rn(silu_f(acc[i][j][2]) * acc[i][j][3]);
            }
        }
    }
}

// ---------------- 6) combine (float4) ---------------------------
__global__ void combine_kernel(float* __restrict__ out) {
    int s = blockIdx.x;
    int e1 = g_e1[s], e2 = g_e2[s];
    int s1 = g_slot1[s], s2 = g_slot2[s];
    float w1 = g_g1[s], w2 = g_g2[s];
    const float4* y1 = (s1 < CAPQ) ? (const float4*)(g_Y + ((size_t)e1 * CAPQ + s1) * H_DIM) : nullptr;
    const float4* y2 = (s2 < CAPQ) ? (const float4*)(g_Y + ((size_t)e2 * CAPQ + s2) * H_DIM) : nullptr;
    float4* o = (float4*)(out + (size_t)s * H_DIM);
    for (int h = threadIdx.x; h < H_DIM / 4; h += blockDim.x) {
        float4 v = make_float4(0.f, 0.f, 0.f, 0.f);
        if (y1) {
            float4 a = y1[h];
            v.x += w1 * a.x; v.y += w1 * a.y; v.z += w1 * a.z; v.w += w1 * a.w;
        }
        if (y2) {
            float4 a = y2[h];
            v.x += w2 * a.x; v.y += w2 * a.y; v.z += w2 * a.z; v.w += w2 * a.w;
        }
        o[h] = v;
    }
}

// ---------------- launch ----------------------------------------
extern "C" void kernel_launch(void* const* d_in, const int* in_sizes, int n_in,
                              void* d_out, int out_size) {
    const float* x   = (const float*)d_in[0];   // [S, H]
    const float* gw  = (const float*)d_in[1];   // [E, H]
    const float* w13 = (const float*)d_in[2];   // [E, 2I, H]
    const float* w2  = (const float*)d_in[3];   // [E, H, I]
    float* out = (float*)d_out;

    __half *Xh, *W13h, *W2h, *Ah;
    float *Yd;
    cudaGetSymbolAddress((void**)&Xh,   g_Xh);
    cudaGetSymbolAddress((void**)&W13h, g_W13h);
    cudaGetSymbolAddress((void**)&W2h,  g_W2h);
    cudaGetSymbolAddress((void**)&Ah,   g_Ah);
    cudaGetSymbolAddress((void**)&Yd,   g_Y);

    static bool attr_set = false;
    if (!attr_set) {
        cudaFuncSetAttribute(gemm_hmma<0>, cudaFuncAttributeMaxDynamicSharedMemorySize, SMEM_TOTAL);
        cudaFuncSetAttribute(gemm_hmma<1>, cudaFuncAttributeMaxDynamicSharedMemorySize, SMEM_TOTAL);
        attr_set = true;
    }

    gate_kernel<<<S_TOK, 256>>>(x, gw);
    scan_kernel<<<1, 512>>>();
    gather_kernel<<<S_TOK * 2, 256>>>(x);

    // weight conversion (w13 row-interleaved, w2 flat)
    cvt13_kernel<<<E_NUM * 2 * I_DIM, 128>>>(w13);
    {
        int n2 = (int)((size_t)E_NUM * H_DIM * I_DIM / 4);
        cvt_kernel<<<4096, 256>>>((const float4*)w2, (uint2*)W2h, n2);
    }

    // GEMM1 fused: Ah[e] = silu(Xh @ w1^T) * (Xh @ w3^T)  (CAP x I fp16)
    {
        dim3 grid(CAPQ / BM, (2 * I_DIM) / BN, E_NUM);
        gemm_hmma<1><<<grid, NTHREADS, SMEM_TOTAL>>>(
            Xh, (size_t)CAPQ * H_DIM,
            W13h, (size_t)2 * I_DIM * H_DIM,
            nullptr, 0,
            Ah, (size_t)I_DIM,
            2 * I_DIM, H_DIM);
    }
    // GEMM2: Y[e] = Ah[e] (CAP x I) @ W2h[e]^T (H x I) -> CAP x H (fp32)
    {
        dim3 grid(CAPQ / BM, H_DIM / BN, E_NUM);
        gemm_hmma<0><<<grid, NTHREADS, SMEM_TOTAL>>>(
            Ah, (size_t)CAPQ * I_DIM,
            W2h, (size_t)H_DIM * I_DIM,
            Yd, (size_t)CAPQ * H_DIM,
            nullptr, 0,
            H_DIM, I_DIM);
    }
    combine_kernel<<<S_TOK, 256>>>(out);
}

// round 17
// speedup vs baseline: 1.0017x; 1.0000x over previous
#include <cuda_runtime.h>
#include <cuda_fp16.h>
#include <math.h>
#include <stdint.h>

#define S_TOK 4096
#define H_DIM 2048
#define I_DIM 7168
#define E_NUM 8
#define CAPQ  2048

// GEMM tile config (fp16 operands)
#define BM 128
#define BN 256
#define BK 64                    // halves per K stage (128 bytes/row)
#define NSTAGE 4
#define STAGE_BYTES 49152        // A 16KB + B 32KB
#define SMEM_TOTAL (1024 + NSTAGE * STAGE_BYTES)
#define NTHREADS 512

// ---------------- device scratch ----------
__device__ int    g_e1[S_TOK], g_e2[S_TOK];
__device__ float  g_g1[S_TOK], g_g2[S_TOK];
__device__ int    g_slot1[S_TOK], g_slot2[S_TOK];
__device__ int    g_used[E_NUM];
__device__ __half g_Xh  [(size_t)E_NUM * CAPQ * H_DIM];           // 67 MB
__device__ __half g_W13h[(size_t)E_NUM * 2 * I_DIM * H_DIM];      // 470 MB (row-interleaved w1/w3)
__device__ __half g_W2h [(size_t)E_NUM * H_DIM * I_DIM];          // 235 MB
__device__ __half g_Ah  [(size_t)E_NUM * CAPQ * I_DIM];           // 235 MB
__device__ float  g_Y   [(size_t)E_NUM * CAPQ * H_DIM];           // 134 MB

// ---------------- PTX helpers ----------------
__device__ __forceinline__ uint32_t smem_u32(const void* p) {
    uint32_t a;
    asm("{ .reg .u64 t; cvta.to.shared.u64 t, %1; cvt.u32.u64 %0, t; }" : "=r"(a) : "l"(p));
    return a;
}
__device__ __forceinline__ void cp16(uint32_t dst, const void* src) {
    asm volatile("cp.async.cg.shared.global [%0], [%1], 16;" :: "r"(dst), "l"(src));
}
#define CP_COMMIT() asm volatile("cp.async.commit_group;")
#define CP_WAIT(n)  asm volatile("cp.async.wait_group %0;" :: "n"(n))

#define LDSM4(r0, r1, r2, r3, a) \
    asm volatile("ldmatrix.sync.aligned.m8n8.x4.shared.b16 {%0,%1,%2,%3}, [%4];" \
        : "=r"(r0), "=r"(r1), "=r"(r2), "=r"(r3) : "r"(a))

__device__ __forceinline__ void mma_f16(float* c, const uint32_t* a, const uint32_t* b) {
    asm volatile("mma.sync.aligned.m16n8k16.row.col.f32.f16.f16.f32 "
        "{%0,%1,%2,%3}, {%4,%5,%6,%7}, {%8,%9}, {%0,%1,%2,%3};"
        : "+f"(c[0]), "+f"(c[1]), "+f"(c[2]), "+f"(c[3])
        : "r"(a[0]), "r"(a[1]), "r"(a[2]), "r"(a[3]), "r"(b[0]), "r"(b[1]));
}

#define SWZ(o) ((o) ^ (((o) >> 3) & 0x70))

__device__ __forceinline__ float silu_f(float g) { return g / (1.f + expf(-g)); }

// ---------------- 1) gating ----------------------
__global__ void gate_kernel(const float* __restrict__ x, const float* __restrict__ gw) {
    int s = blockIdx.x;
    int w = threadIdx.x >> 5, lane = threadIdx.x & 31;
    const float* xr = x + (size_t)s * H_DIM;
    const float* gr = gw + (size_t)w * H_DIM;
    float acc = 0.f;
    for (int h = lane; h < H_DIM; h += 32) acc += xr[h] * gr[h];
    #pragma unroll
    for (int o = 16; o; o >>= 1) acc += __shfl_xor_sync(0xffffffff, acc, o);
    __shared__ float logit[E_NUM];
    if (lane == 0) logit[w] = acc;
    __syncthreads();
    if (threadIdx.x == 0) {
        int i1 = 0; float b1 = logit[0];
        #pragma unroll
        for (int e = 1; e < E_NUM; e++) if (logit[e] > b1) { b1 = logit[e]; i1 = e; }
        int i2 = -1; float b2 = -1e30f;
        #pragma unroll
        for (int e = 0; e < E_NUM; e++) if (e != i1 && logit[e] > b2) { b2 = logit[e]; i2 = e; }
        float p2 = expf(b2 - b1);
        float inv = 1.f / (1.f + p2);
        g_e1[s] = i1; g_e2[s] = i2;
        g_g1[s] = inv; g_g2[s] = p2 * inv;
    }
}

// ---------------- 2) routing scan ----------------------------
__global__ void scan_kernel() {
    __shared__ int sh[512][16];
    __shared__ int cnt1[E_NUM];
    int t = threadIdx.x;
    int c[16];
    #pragma unroll
    for (int i = 0; i < 16; i++) c[i] = 0;
    int base = t * 8;
    #pragma unroll
    for (int j = 0; j < 8; j++) { c[g_e1[base + j]]++; c[8 + g_e2[base + j]]++; }
    #pragma unroll
    for (int i = 0; i < 16; i++) sh[t][i] = c[i];
    __syncthreads();
    for (int off = 1; off < 512; off <<= 1) {
        int v[16];
        if (t >= off) {
            #pragma unroll
            for (int i = 0; i < 16; i++) v[i] = sh[t - off][i];
        }
        __syncthreads();
        if (t >= off) {
            #pragma unroll
            for (int i = 0; i < 16; i++) sh[t][i] += v[i];
        }
        __syncthreads();
    }
    if (t == 0) {
        #pragma unroll
        for (int e = 0; e < E_NUM; e++) cnt1[e] = sh[511][e];
    }
    __syncthreads();
    int off1[E_NUM], off2[E_NUM];
    #pragma unroll
    for (int e = 0; e < E_NUM; e++) {
        off1[e] = sh[t][e] - c[e];
        off2[e] = sh[t][8 + e] - c[8 + e];
    }
    #pragma unroll
    for (int j = 0; j < 8; j++) {
        int s = base + j;
        int e1 = g_e1[s], e2 = g_e2[s];
        g_slot1[s] = off1[e1]++;
        g_slot2[s] = cnt1[e2] + off2[e2]++;
    }
    if (t < E_NUM) {
        int u = sh[511][t] + sh[511][8 + t];
        g_used[t] = (u > CAPQ) ? CAPQ : u;
    }
}

// ---------------- 3) dispatch gather (fp32 -> fp16) ------------
__global__ void gather_kernel(const float* __restrict__ x) {
    int b = blockIdx.x;
    int s = b >> 1, ch = b & 1;
    int e    = ch ? g_e2[s]    : g_e1[s];
    int slot = ch ? g_slot2[s] : g_slot1[s];
    if (slot >= CAPQ) return;
    const float4* src = (const float4*)(x + (size_t)s * H_DIM);
    uint2*        dst = (uint2*)(g_Xh + ((size_t)e * CAPQ + slot) * H_DIM);
    for (int i = threadIdx.x; i < H_DIM / 4; i += blockDim.x) {
        float4 v = src[i];
        __half2 h0 = __floats2half2_rn(v.x, v.y);
        __half2 h1 = __floats2half2_rn(v.z, v.w);
        uint2 o; o.x = *(uint32_t*)&h0; o.y = *(uint32_t*)&h1;
        dst[i] = o;
    }
}

// ---------------- 3b) w13 convert + row interleave --------------
// dst row r (within expert): r even -> w1 row r/2; r odd -> w3 row r/2 (src row I + r/2)
__global__ void cvt13_kernel(const float* __restrict__ src) {
    int d = blockIdx.x;                      // dst row, global over E*2I
    int e = d / (2 * I_DIM);
    int r = d - e * 2 * I_DIM;
    int n = (r & 1) ? (I_DIM + (r >> 1)) : (r >> 1);
    const float4* s4 = (const float4*)(src + ((size_t)e * 2 * I_DIM + n) * H_DIM);
    uint2* dst = (uint2*)(g_W13h + (size_t)d * H_DIM);
    for (int i = threadIdx.x; i < H_DIM / 4; i += blockDim.x) {
        float4 v = s4[i];
        __half2 h0 = __floats2half2_rn(v.x, v.y);
        __half2 h1 = __floats2half2_rn(v.z, v.w);
        uint2 o; o.x = *(uint32_t*)&h0; o.y = *(uint32_t*)&h1;
        dst[i] = o;
    }
}

// ---------------- 3c) flat weight convert fp32 -> fp16 ----------
__global__ void cvt_kernel(const float4* __restrict__ src, uint2* __restrict__ dst, int n4) {
    int i = blockIdx.x * blockDim.x + threadIdx.x;
    int stride = gridDim.x * blockDim.x;
    for (; i < n4; i += stride) {
        float4 v = src[i];
        __half2 h0 = __floats2half2_rn(v.x, v.y);
        __half2 h1 = __floats2half2_rn(v.z, v.w);
        uint2 o; o.x = *(uint32_t*)&h0; o.y = *(uint32_t*)&h1;
        dst[i] = o;
    }
}

// ---------------- 4) fp16 mma grouped GEMM NT ------------------
// C[m][n] = sum_k A[m][k]*B[n][k];  128x256 CTA, 16 warps (2x8), warp 64x32
// MODE 0: plain fp32 C  (N = logical cols)
// MODE 1: fused silu(even)*odd -> fp16 out, out cols = N/2, row stride strideO
template <int MODE>
__global__ void __launch_bounds__(NTHREADS, 1) gemm_hmma(
    const __half* __restrict__ Abase, size_t strideA,
    const __half* __restrict__ Bbase, size_t strideB,
    float* __restrict__ Cbase, size_t strideC,
    __half* __restrict__ Obase, size_t strideO,
    int N, int K)    // K in halves
{
    extern __shared__ char smem_raw[];
    int e = blockIdx.z;
    int mrow = blockIdx.x * BM;
    if (mrow >= g_used[e]) return;
    int ncol = blockIdx.y * BN;
    const __half* A = Abase + (size_t)e * strideA + (size_t)mrow * K;
    const __half* B = Bbase + (size_t)e * strideB + (size_t)ncol * K;

    uint32_t sb = (smem_u32(smem_raw) + 1023u) & ~1023u;
    int tid  = threadIdx.x;
    int lane = tid & 31;
    int wid  = tid >> 5;
    int wm = wid >> 3;            // 0..1  (M, 64 rows each)
    int wn = wid & 7;             // 0..7  (N, 32 cols each)

    const int arow = tid >> 2, acb = (tid & 3) * 32;
    const int brow = tid >> 1, bcb = (tid & 1) * 64;
    const __half* Ag = A + (size_t)arow * K + (acb >> 1);
    const __half* Bg = B + (size_t)brow * K + (bcb >> 1);
    uint32_t a_sw[2], b_sw[4];
    #pragma unroll
    for (int j = 0; j < 2; j++) a_sw[j] = SWZ((uint32_t)(arow * 128 + acb + j * 16));
    #pragma unroll
    for (int j = 0; j < 4; j++) b_sw[j] = SWZ((uint32_t)(brow * 128 + bcb + j * 16));

    uint32_t a_off[4];
    #pragma unroll
    for (int i = 0; i < 4; i++) {
        uint32_t r = (uint32_t)(wm * 64 + i * 16 + (lane & 15));
        a_off[i] = r * 128 + ((lane >> 4) & 1) * 16;
    }
    uint32_t b_off[2];
    #pragma unroll
    for (int jp = 0; jp < 2; jp++) {
        uint32_t r = (uint32_t)(wn * 32 + jp * 16 + (lane & 7) + ((lane >> 4) & 1) * 8);
        b_off[jp] = r * 128 + ((lane >> 3) & 1) * 16;
    }

    float acc[4][4][4];
    #pragma unroll
    for (int i = 0; i < 4; i++)
        #pragma unroll
        for (int j = 0; j < 4; j++)
            #pragma unroll
            for (int q = 0; q < 4; q++) acc[i][j][q] = 0.f;

    const int KST = K / BK;

    #pragma unroll
    for (int s = 0; s < NSTAGE - 1; s++) {
        const __half* ag = Ag + s * BK;
        const __half* bg = Bg + s * BK;
        uint32_t ab = sb + s * STAGE_BYTES, bb = ab + 16384;
        #pragma unroll
        for (int j = 0; j < 2; j++) cp16(ab + a_sw[j], ag + j * 8);
        #pragma unroll
        for (int j = 0; j < 4; j++) cp16(bb + b_sw[j], bg + j * 8);
        CP_COMMIT();
    }

    for (int k = 0; k < KST; k++) {
        int buf = k & (NSTAGE - 1);
        CP_WAIT(NSTAGE - 2);
        __syncthreads();

        int ls = k + NSTAGE - 1;
        if (ls < KST) {
            int lb = ls & (NSTAGE - 1);
            const __half* ag = Ag + ls * BK;
            const __half* bg = Bg + ls * BK;
            uint32_t ab = sb + lb * STAGE_BYTES, bb = ab + 16384;
            #pragma unroll
            for (int j = 0; j < 2; j++) cp16(ab + a_sw[j], ag + j * 8);
            #pragma unroll
            for (int j = 0; j < 4; j++) cp16(bb + b_sw[j], bg + j * 8);
        }
        CP_COMMIT();

        uint32_t asb = sb + buf * STAGE_BYTES;
        uint32_t bsb = asb + 16384;
        #pragma unroll
        for (int kb = 0; kb < 4; kb++) {
            uint32_t afrag[4][4], bfrag[4][2];
            #pragma unroll
            for (int i = 0; i < 4; i++) {
                uint32_t addr = asb + SWZ(a_off[i] + kb * 32);
                LDSM4(afrag[i][0], afrag[i][1], afrag[i][2], afrag[i][3], addr);
            }
            #pragma unroll
            for (int jp = 0; jp < 2; jp++) {
                uint32_t addr = bsb + SWZ(b_off[jp] + kb * 32);
                LDSM4(bfrag[2*jp][0], bfrag[2*jp][1], bfrag[2*jp+1][0], bfrag[2*jp+1][1], addr);
            }
            #pragma unroll
            for (int i = 0; i < 4; i++)
                #pragma unroll
                for (int j = 0; j < 4; j++)
                    mma_f16(acc[i][j], afrag[i], bfrag[j]);
        }
    }

    int g  = lane >> 2;
    int t4 = lane & 3;
    if (MODE == 0) {
        float* C = Cbase + (size_t)e * strideC + (size_t)mrow * N + ncol;
        #pragma unroll
        for (int i = 0; i < 4; i++) {
            int r0 = wm * 64 + i * 16 + g;
            #pragma unroll
            for (int j = 0; j < 4; j++) {
                int cb = wn * 32 + j * 8 + 2 * t4;
                float* p0 = C + (size_t)r0 * N + cb;
                float* p1 = p0 + (size_t)8 * N;
                *(float2*)p0 = make_float2(acc[i][j][0], acc[i][j][1]);
                *(float2*)p1 = make_float2(acc[i][j][2], acc[i][j][3]);
            }
        }
    } else {
        // fused: even col = g, odd col = u  ->  silu(g)*u, out col = cb/2
        __half* O = Obase + (size_t)e * strideO * 0 + ((size_t)e * CAPQ + mrow) * strideO + (ncol >> 1);
        #pragma unroll
        for (int i = 0; i < 4; i++) {
            int r0 = wm * 64 + i * 16 + g;
            #pragma unroll
            for (int j = 0; j < 4; j++) {
                int co = wn * 16 + j * 4 + t4;
                __half* p0 = O + (size_t)r0 * strideO + co;
                __half* p1 = p0 + (size_t)8 * strideO;
                *p0 = __float2half_rn(silu_f(acc[i][j][0]) * acc[i][j][1]);
                *p1 = __float2half_rn(silu_f(acc[i][j][2]) * acc[i][j][3]);
            }
        }
    }
}

// ---------------- 6) combine (float4) ---------------------------
__global__ void combine_kernel(float* __restrict__ out) {
    int s = blockIdx.x;
    int e1 = g_e1[s], e2 = g_e2[s];
    int s1 = g_slot1[s], s2 = g_slot2[s];
    float w1 = g_g1[s], w2 = g_g2[s];
    const float4* y1 = (s1 < CAPQ) ? (const float4*)(g_Y + ((size_t)e1 * CAPQ + s1) * H_DIM) : nullptr;
    const float4* y2 = (s2 < CAPQ) ? (const float4*)(g_Y + ((size_t)e2 * CAPQ + s2) * H_DIM) : nullptr;
    float4* o = (float4*)(out + (size_t)s * H_DIM);
    for (int h = threadIdx.x; h < H_DIM / 4; h += blockDim.x) {
        float4 v = make_float4(0.f, 0.f, 0.f, 0.f);
        if (y1) {
            float4 a = y1[h];
            v.x += w1 * a.x; v.y += w1 * a.y; v.z += w1 * a.z; v.w += w1 * a.w;
        }
        if (y2) {
            float4 a = y2[h];
            v.x += w2 * a.x; v.y += w2 * a.y; v.z += w2 * a.z; v.w += w2 * a.w;
        }
        o[h] = v;
    }
}

// ---------------- launch ----------------------------------------
extern "C" void kernel_launch(void* const* d_in, const int* in_sizes, int n_in,
                              void* d_out, int out_size) {
    const float* x   = (const float*)d_in[0];   // [S, H]
    const float* gw  = (const float*)d_in[1];   // [E, H]
    const float* w13 = (const float*)d_in[2];   // [E, 2I, H]
    const float* w2  = (const float*)d_in[3];   // [E, H, I]
    float* out = (float*)d_out;

    __half *Xh, *W13h, *W2h, *Ah;
    float *Yd;
    cudaGetSymbolAddress((void**)&Xh,   g_Xh);
    cudaGetSymbolAddress((void**)&W13h, g_W13h);
    cudaGetSymbolAddress((void**)&W2h,  g_W2h);
    cudaGetSymbolAddress((void**)&Ah,   g_Ah);
    cudaGetSymbolAddress((void**)&Yd,   g_Y);

    static bool attr_set = false;
    if (!attr_set) {
        cudaFuncSetAttribute(gemm_hmma<0>, cudaFuncAttributeMaxDynamicSharedMemorySize, SMEM_TOTAL);
        cudaFuncSetAttribute(gemm_hmma<1>, cudaFuncAttributeMaxDynamicSharedMemorySize, SMEM_TOTAL);
        attr_set = true;
    }

    gate_kernel<<<S_TOK, 256>>>(x, gw);
    scan_kernel<<<1, 512>>>();
    gather_kernel<<<S_TOK * 2, 256>>>(x);

    // weight conversion (w13 row-interleaved, w2 flat)
    cvt13_kernel<<<E_NUM * 2 * I_DIM, 128>>>(w13);
    {
        int n2 = (int)((size_t)E_NUM * H_DIM * I_DIM / 4);
        cvt_kernel<<<4096, 256>>>((const float4*)w2, (uint2*)W2h, n2);
    }

    // GEMM1 fused: Ah[e] = silu(Xh @ w1^T) * (Xh @ w3^T)  (CAP x I fp16)
    {
        dim3 grid(CAPQ / BM, (2 * I_DIM) / BN, E_NUM);
        gemm_hmma<1><<<grid, NTHREADS, SMEM_TOTAL>>>(
            Xh, (size_t)CAPQ * H_DIM,
            W13h, (size_t)2 * I_DIM * H_DIM,
            nullptr, 0,
            Ah, (size_t)I_DIM,
            2 * I_DIM, H_DIM);
    }
    // GEMM2: Y[e] = Ah[e] (CAP x I) @ W2h[e]^T (H x I) -> CAP x H (fp32)
    {
        dim3 grid(CAPQ / BM, H_DIM / BN, E_NUM);
        gemm_hmma<0><<<grid, NTHREADS, SMEM_TOTAL>>>(
            Ah, (size_t)CAPQ * I_DIM,
            W2h, (size_t)H_DIM * I_DIM,
            Yd, (size_t)CAPQ * H_DIM,
            nullptr, 0,
            H_DIM, I_DIM);
    }
    combine_kernel<<<S_TOK, 256>>>(out);
}